// round 14
// baseline (speedup 1.0000x reference)
#include <cuda_runtime.h>
#include <cuda_fp16.h>
#include <cstdint>

// ============================================================================
// DistNet: out[n] = sigmoid((max(0, ||x||^2 + min_p(||p||^2 - 2 x.p)) + alpha)/beta)
// R14: m64 PER WARP (A-frags = 128 regs, occ 1 @ 255 regs) -> B-side LDSM
// bytes and instruction count per MAC halved (0.0625 -> 0.031 B/MAC),
// attacking the smem-crossbar/MIO co-limiter. MTILE=64, grid 1024 (98.8%
// packing). 8 warps = 4 groups x 2; group owns 512 pts, two-stage pair
// pipeline with named barriers (R7 scheme); warp = m64 x n32 per sub-chunk.
// ============================================================================

static constexpr int NROWS  = 65536;
static constexpr int DIM    = 128;
static constexpr int NPTS   = 2048;
static constexpr int MTILE  = 64;
static constexpr int SUBPTS = 64;            // points per sub-chunk
static constexpr int NSUB   = 512 / SUBPTS;  // 8 sub-chunks per group

#define LOG1000F 6.9077542789816375f

__device__ __align__(16) __half g_pts[NPTS * DIM];  // fp16 points, K-major
__device__ __align__(16) __half g_pn[NPTS];         // ||p||^2 (fp16)

// smem layout (dynamic)
static constexpr int OFF_X      = 0;                    // 64 x 256B = 16384
static constexpr int OFF_B      = 16384;
static constexpr int BUFBYTES   = SUBPTS * 256;         // 16384 per stage
static constexpr int BUFSTRIDE  = BUFBYTES + 128;       // + pn (128B)
static constexpr int GROUPBYTES = 2 * BUFSTRIDE;        // double buffer
static constexpr int OFF_XN     = OFF_B + 4 * GROUPBYTES;  // 148480, 256B
static constexpr int OFF_MIN    = OFF_XN + 256;            // 8 x 64 floats
static constexpr int SMEM_BYTES = OFF_MIN + 2048 + 128;    // ~151KB -> occ 1

// ---------------------------------------------------------------------------
__device__ __forceinline__ uint32_t smem_u32(const void* p) {
    uint32_t a;
    asm("{ .reg .u64 t; cvta.to.shared.u64 t, %1; cvt.u32.u64 %0, t; }"
        : "=r"(a) : "l"(p));
    return a;
}

__device__ __forceinline__ void cp_async16(uint32_t dst, const void* src) {
    asm volatile("cp.async.cg.shared.global [%0], [%1], 16;"
                 :: "r"(dst), "l"(src) : "memory");
}

#define LDMATRIX_X4(R, ADDR)                                                   \
    asm volatile("ldmatrix.sync.aligned.m8n8.x4.shared.b16 {%0,%1,%2,%3}, [%4];" \
                 : "=r"((R)[0]), "=r"((R)[1]), "=r"((R)[2]), "=r"((R)[3])       \
                 : "r"(ADDR))

#define MMA16816H(C, A, B0, B1)                                                \
    asm volatile("mma.sync.aligned.m16n8k16.row.col.f16.f16.f16.f16 "          \
                 "{%0,%1}, {%2,%3,%4,%5}, {%6,%7}, {%0,%1};"                   \
                 : "+r"((C)[0]), "+r"((C)[1])                                  \
                 : "r"((A)[0]), "r"((A)[1]), "r"((A)[2]), "r"((A)[3]),         \
                   "r"(B0), "r"(B1))

// ---------------------------------------------------------------------------
// Prep: points f32 -> fp16 row-major + ||p||^2 (fp16)
__global__ void distnet_prep(const float* __restrict__ pts) {
    int p = blockIdx.x;
    int t = threadIdx.x;  // 128 = DIM
    float v = pts[p * DIM + t];
    g_pts[p * DIM + t] = __float2half(v);
    float s = v * v;
#pragma unroll
    for (int o = 16; o > 0; o >>= 1) s += __shfl_xor_sync(0xffffffffu, s, o);
    __shared__ float ws[4];
    if ((t & 31) == 0) ws[t >> 5] = s;
    __syncthreads();
    if (t == 0) g_pn[p] = __float2half(ws[0] + ws[1] + ws[2] + ws[3]);
}

// ---------------------------------------------------------------------------
// Group-scope async copy of one 64-point sub-chunk (16KB B + 128B pn).
// tg in [0,64). base = first point index of this group's 512-point span.
__device__ __forceinline__ void issue_sub(uint32_t dst, int base, int sub, int tg) {
    const char* src = (const char*)g_pts + ((size_t)base + sub * SUBPTS) * 256;
#pragma unroll
    for (int u = 0; u < 16; u++) {
        int i = tg + u * 64;             // 0..1023 16B units
        int n = i >> 4, c = i & 15;
        cp_async16(dst + n * 256 + ((c ^ (n & 7)) * 16), src + i * 16);
    }
    if (tg < 8)
        cp_async16(dst + BUFBYTES + tg * 16,
                   (const char*)g_pn + ((size_t)base + sub * SUBPTS) * 2 + tg * 16);
    asm volatile("cp.async.commit_group;" ::: "memory");
}

// ---------------------------------------------------------------------------
__global__ void __launch_bounds__(256, 1)
distnet_main(const float* __restrict__ x, const float* __restrict__ beta_raw,
             float* __restrict__ out) {
    extern __shared__ char smem[];
    const uint32_t sb = smem_u32(smem);
    const int tid   = threadIdx.x;
    const int lane  = tid & 31;
    const int wid   = tid >> 5;        // 0..7
    const int group = wid >> 1;        // 0..3, owns points [512*group, +512)
    const int nhalf = wid & 1;         // warp's 32-pt half of each 64-pt sub-chunk
    const int tg    = tid & 63;        // thread index within group
    const int row0  = blockIdx.x * MTILE;

    const uint32_t buf0 = sb + OFF_B + group * GROUPBYTES;
    const uint32_t buf1 = buf0 + BUFSTRIDE;
    const int pbase = group * 512;

    issue_sub(buf0, pbase, 0, tg);     // prefetch sub-chunk 0

    // ---- X tile: 64 rows x 256B fp16, 4 threads per row + ||x||^2
    {
        int sub = tid & 3;
        int r   = tid >> 2;            // 0..63
        const float4* src = (const float4*)(x + (size_t)(row0 + r) * DIM);
        float s = 0.f;
#pragma unroll
        for (int j = 0; j < 4; j++) {
            int c = j * 4 + sub;       // 16B fp16 unit
            float4 v0 = src[c * 2], v1 = src[c * 2 + 1];
            s += v0.x * v0.x + v0.y * v0.y + v0.z * v0.z + v0.w * v0.w;
            s += v1.x * v1.x + v1.y * v1.y + v1.z * v1.z + v1.w * v1.w;
            __half2 p0 = __floats2half2_rn(v0.x, v0.y);
            __half2 p1 = __floats2half2_rn(v0.z, v0.w);
            __half2 p2 = __floats2half2_rn(v1.x, v1.y);
            __half2 p3 = __floats2half2_rn(v1.z, v1.w);
            uint4 pk;
            pk.x = *(uint32_t*)&p0; pk.y = *(uint32_t*)&p1;
            pk.z = *(uint32_t*)&p2; pk.w = *(uint32_t*)&p3;
            *(uint4*)(smem + OFF_X + r * 256 + ((c ^ (r & 7)) * 16)) = pk;
        }
        s += __shfl_xor_sync(0xffffffffu, s, 1);
        s += __shfl_xor_sync(0xffffffffu, s, 2);
        if (sub == 0) ((float*)(smem + OFF_XN))[r] = s;
    }
    __syncthreads();

    // ---- A fragments: EVERY warp holds the full m64 tile (4 m16 x 8 k16)
    uint32_t afr[4][8][4];             // 128 registers
    {
        int ar = lane & 15, ah = lane >> 4;
#pragma unroll
        for (int mt = 0; mt < 4; mt++) {
            int r = mt * 16 + ar;
#pragma unroll
            for (int k = 0; k < 8; k++) {
                uint32_t addr = sb + OFF_X + r * 256 + (((2 * k + ah) ^ (r & 7)) * 16);
                LDMATRIX_X4(afr[mt][k], addr);
            }
        }
    }

    const int q  = lane & 3;   // col pair within n8
    const int rp = lane >> 2;  // row within 8
    const uint32_t br_ = lane & 7, bh = lane >> 3;  // B ldmatrix lane mapping
    const int barid = group + 1;

    const __half2 mtwo = __float2half2_rn(-2.0f);
    const __half2 biginit = __float2half2_rn(60000.0f);
    // rmin2[mt][j]: row mt*16 + j*8 + rp, two cols (2q, 2q+1)
    __half2 rmin2[4][2] = {{biginit, biginit}, {biginit, biginit},
                           {biginit, biginit}, {biginit, biginit}};

    // ---- mainloop: group-private two-stage pipeline over 8 x 64-pt sub-chunks
#pragma unroll 1
    for (int i = 0; i < NSUB; i++) {
        uint32_t buf = (i & 1) ? buf1 : buf0;
        asm volatile("cp.async.wait_group 0;" ::: "memory");
        asm volatile("bar.sync %0, 64;" :: "r"(barid) : "memory");
        if (i + 1 < NSUB)
            issue_sub((i & 1) ? buf0 : buf1, pbase, i + 1, tg);

        const __half2* pnb = (const __half2*)(smem + (buf - sb) + BUFBYTES);
        const uint32_t bl = buf + nhalf * 8192 + br_ * 256;  // warp's n32 span
#pragma unroll
        for (int g = 0; g < 4; g++) {   // 4 n8-groups of this warp's n32
            uint32_t bfr[4][4];
#pragma unroll
            for (int kk = 0; kk < 4; kk++) {
                uint32_t addr = bl + g * 2048 + (((4 * kk + bh) ^ br_) * 16);
                LDMATRIX_X4(bfr[kk], addr);
            }
            uint32_t acc[4][2] = {{0u,0u},{0u,0u},{0u,0u},{0u,0u}};
#pragma unroll
            for (int kk = 0; kk < 4; kk++) {
#pragma unroll
                for (int mt = 0; mt < 4; mt++)
                    MMA16816H(acc[mt], afr[mt][2 * kk],     bfr[kk][0], bfr[kk][1]);
#pragma unroll
                for (int mt = 0; mt < 4; mt++)
                    MMA16816H(acc[mt], afr[mt][2 * kk + 1], bfr[kk][2], bfr[kk][3]);
            }
            __half2 pp = pnb[nhalf * 16 + g * 4 + q];
#pragma unroll
            for (int mt = 0; mt < 4; mt++) {
                rmin2[mt][0] = __hmin2(rmin2[mt][0],
                                       __hfma2(mtwo, *(__half2*)&acc[mt][0], pp));
                rmin2[mt][1] = __hmin2(rmin2[mt][1],
                                       __hfma2(mtwo, *(__half2*)&acc[mt][1], pp));
            }
        }
    }

    // ---- reduce across the lane-quad (4 col-pairs = 8 cols) within each warp
    float rmin[4][2];
#pragma unroll
    for (int mt = 0; mt < 4; mt++) {
#pragma unroll
        for (int j = 0; j < 2; j++) {
            uint32_t v = *(uint32_t*)&rmin2[mt][j];
            uint32_t v1 = __shfl_xor_sync(0xffffffffu, v, 1);
            __half2 h = __hmin2(*(__half2*)&v, *(__half2*)&v1);
            uint32_t hv = *(uint32_t*)&h;
            uint32_t v2 = __shfl_xor_sync(0xffffffffu, hv, 2);
            h = __hmin2(h, *(__half2*)&v2);
            rmin[mt][j] = fminf(__low2float(h), __high2float(h));
        }
    }
    // rmin[mt][j] = min over this warp's (group,nhalf) pts for row mt*16+j*8+rp

    // ---- combine all 8 warps via smem, then epilogue
    float* minbuf = (float*)(smem + OFF_MIN);   // [8][64]
    if (q == 0) {
#pragma unroll
        for (int mt = 0; mt < 4; mt++)
#pragma unroll
            for (int j = 0; j < 2; j++)
                minbuf[wid * 64 + mt * 16 + j * 8 + rp] = rmin[mt][j];
    }
    __syncthreads();
    if (tid < MTILE) {
        const float* xn_s = (const float*)(smem + OFF_XN);
        float brv  = beta_raw[0];
        float beta = fmaxf(brv, 0.f) + log1pf(__expf(-fabsf(brv)));  // softplus
        float mn = minbuf[tid];
#pragma unroll
        for (int w = 1; w < 8; w++) mn = fminf(mn, minbuf[w * 64 + tid]);
        float md  = fmaxf(xn_s[tid] + mn, 0.f);
        float arg = (md - beta * LOG1000F) / beta;
        out[row0 + tid] = 1.f / (1.f + __expf(-arg));
    }
}

// ---------------------------------------------------------------------------
extern "C" void kernel_launch(void* const* d_in, const int* in_sizes, int n_in,
                              void* d_out, int out_size) {
    const float* x    = (const float*)d_in[0];   // [65536,128]
    const float* pts  = (const float*)d_in[1];   // [2048,128]
    const float* braw = (const float*)d_in[2];   // [1]
    float* out = (float*)d_out;                  // [65536]

    cudaFuncSetAttribute(distnet_main, cudaFuncAttributeMaxDynamicSharedMemorySize,
                         SMEM_BYTES);

    distnet_prep<<<NPTS, DIM>>>(pts);
    distnet_main<<<NROWS / MTILE, 256, SMEM_BYTES>>>(x, braw, out);
}

// round 15
// speedup vs baseline: 1.0663x; 1.0663x over previous
#include <cuda_runtime.h>
#include <cuda_fp16.h>
#include <cstdint>

// ============================================================================
// DistNet: out[n] = sigmoid((max(0, ||x||^2 + min_p(||p||^2 - 2 x.p)) + alpha)/beta)
// R15: R7 fp16 HMMA pair-pipeline core at grid 2048 (64 rows x 1024 pts per
// CTA -> T_CTA halved, wave quantization loss halved) with the R13 in-kernel
// ticket combine (no init/epilogue kernels): per-half row-mins stored to
// global, last CTA of each tile fuses the sigmoid epilogue + resets ticket.
// ============================================================================

static constexpr int NROWS  = 65536;
static constexpr int DIM    = 128;
static constexpr int NPTS   = 2048;
static constexpr int MTILE  = 64;
static constexpr int NTILES = NROWS / MTILE;   // 1024
static constexpr int SUBPTS = 32;              // points per sub-chunk
static constexpr int NSUB   = 256 / SUBPTS;    // 8 sub-chunks per pair (256 pts)

#define LOG1000F 6.9077542789816375f

__device__ __align__(16) __half g_pts[NPTS * DIM];  // fp16 points, K-major
__device__ __align__(16) __half g_pn[NPTS];         // ||p||^2 (fp16)
__device__ float g_hmin[2 * NROWS];                 // per-half row mins
__device__ int   g_tick[NTILES];                    // zero-init tickets

// smem layout (dynamic)
static constexpr int OFF_X     = 0;                    // 64 x 256B = 16384
static constexpr int OFF_B     = 16384;
static constexpr int BUFBYTES  = SUBPTS * 256;         // 8192 per stage buffer
static constexpr int BUFSTRIDE = BUFBYTES + 128;       // + pn (64B) + pad
static constexpr int PAIRBYTES = 2 * BUFSTRIDE;
static constexpr int OFF_XN    = OFF_B + 4 * PAIRBYTES;   // 82944, 256B
static constexpr int OFF_MIN   = OFF_XN + 256;            // [4][64] floats
static constexpr int OFF_FLAG  = OFF_MIN + 1024;          // 1 int
static constexpr int SMEM_BYTES = OFF_FLAG + 128;         // ~84.4KB -> occ 2

// ---------------------------------------------------------------------------
__device__ __forceinline__ uint32_t smem_u32(const void* p) {
    uint32_t a;
    asm("{ .reg .u64 t; cvta.to.shared.u64 t, %1; cvt.u32.u64 %0, t; }"
        : "=r"(a) : "l"(p));
    return a;
}

__device__ __forceinline__ void cp_async16(uint32_t dst, const void* src) {
    asm volatile("cp.async.cg.shared.global [%0], [%1], 16;"
                 :: "r"(dst), "l"(src) : "memory");
}

#define LDMATRIX_X4(R, ADDR)                                                   \
    asm volatile("ldmatrix.sync.aligned.m8n8.x4.shared.b16 {%0,%1,%2,%3}, [%4];" \
                 : "=r"((R)[0]), "=r"((R)[1]), "=r"((R)[2]), "=r"((R)[3])       \
                 : "r"(ADDR))

#define MMA16816H(C, A, B0, B1)                                                \
    asm volatile("mma.sync.aligned.m16n8k16.row.col.f16.f16.f16.f16 "          \
                 "{%0,%1}, {%2,%3,%4,%5}, {%6,%7}, {%0,%1};"                   \
                 : "+r"((C)[0]), "+r"((C)[1])                                  \
                 : "r"((A)[0]), "r"((A)[1]), "r"((A)[2]), "r"((A)[3]),         \
                   "r"(B0), "r"(B1))

// ---------------------------------------------------------------------------
// Prep: points f32 -> fp16 row-major + ||p||^2 (fp16)
__global__ void distnet_prep(const float* __restrict__ pts) {
    int p = blockIdx.x;
    int t = threadIdx.x;  // 128 = DIM
    float v = pts[p * DIM + t];
    g_pts[p * DIM + t] = __float2half(v);
    float s = v * v;
#pragma unroll
    for (int o = 16; o > 0; o >>= 1) s += __shfl_xor_sync(0xffffffffu, s, o);
    __shared__ float ws[4];
    if ((t & 31) == 0) ws[t >> 5] = s;
    __syncthreads();
    if (t == 0) g_pn[p] = __float2half(ws[0] + ws[1] + ws[2] + ws[3]);
}

// ---------------------------------------------------------------------------
// Pair-scope async copy of one 32-point sub-chunk (8KB B + 64B pn).
// base = first point index of this pair's 256-point span. tp in [0,64).
__device__ __forceinline__ void issue_sub(uint32_t dst, int base, int sub, int tp) {
    const char* src = (const char*)g_pts + ((size_t)base + sub * SUBPTS) * 256;
#pragma unroll
    for (int u = 0; u < 8; u++) {
        int i = tp + u * 64;             // 0..511 16B units
        int n = i >> 4, c = i & 15;
        cp_async16(dst + n * 256 + ((c ^ (n & 7)) * 16), src + i * 16);
    }
    if (tp < 4)
        cp_async16(dst + BUFBYTES + tp * 16,
                   (const char*)g_pn + ((size_t)base + sub * SUBPTS) * 2 + tp * 16);
    asm volatile("cp.async.commit_group;" ::: "memory");
}

// ---------------------------------------------------------------------------
__global__ void __launch_bounds__(256, 2)
distnet_main(const float* __restrict__ x, const float* __restrict__ beta_raw,
             float* __restrict__ out) {
    extern __shared__ char smem[];
    const uint32_t sb = smem_u32(smem);
    const int tid   = threadIdx.x;
    const int lane  = tid & 31;
    const int wid   = tid >> 5;        // 0..7
    const int mhalf = wid & 1;         // m32 half of the 64-row tile
    const int pair  = wid >> 1;        // 0..3
    const int tp    = tid & 63;        // thread index within pair
    const int tile  = blockIdx.x >> 1;
    const int half  = blockIdx.x & 1;  // which 1024-pt half of the points
    const int row0  = tile * MTILE;
    const int pbase = half * 1024 + pair * 256;

    const uint32_t buf0 = sb + OFF_B + pair * PAIRBYTES;
    const uint32_t buf1 = buf0 + BUFSTRIDE;

    issue_sub(buf0, pbase, 0, tp);     // prefetch sub-chunk 0

    // ---- X tile: 64 rows x 256B fp16, 4 threads per row + ||x||^2
    {
        int sub = tid & 3;
        int r   = tid >> 2;            // 0..63
        const float4* src = (const float4*)(x + (size_t)(row0 + r) * DIM);
        float s = 0.f;
#pragma unroll
        for (int j = 0; j < 4; j++) {
            int c = j * 4 + sub;       // 16B fp16 unit
            float4 v0 = src[c * 2], v1 = src[c * 2 + 1];
            s += v0.x * v0.x + v0.y * v0.y + v0.z * v0.z + v0.w * v0.w;
            s += v1.x * v1.x + v1.y * v1.y + v1.z * v1.z + v1.w * v1.w;
            __half2 p0 = __floats2half2_rn(v0.x, v0.y);
            __half2 p1 = __floats2half2_rn(v0.z, v0.w);
            __half2 p2 = __floats2half2_rn(v1.x, v1.y);
            __half2 p3 = __floats2half2_rn(v1.z, v1.w);
            uint4 pk;
            pk.x = *(uint32_t*)&p0; pk.y = *(uint32_t*)&p1;
            pk.z = *(uint32_t*)&p2; pk.w = *(uint32_t*)&p3;
            *(uint4*)(smem + OFF_X + r * 256 + ((c ^ (r & 7)) * 16)) = pk;
        }
        s += __shfl_xor_sync(0xffffffffu, s, 1);
        s += __shfl_xor_sync(0xffffffffu, s, 2);
        if (sub == 0) ((float*)(smem + OFF_XN))[r] = s;
    }
    __syncthreads();

    // ---- A fragments: warp owns rows mhalf*32..+31; load once
    uint32_t afr[2][8][4];
    {
        int ar = lane & 15, ah = lane >> 4;
#pragma unroll
        for (int mt = 0; mt < 2; mt++) {
            int r = mhalf * 32 + mt * 16 + ar;
#pragma unroll
            for (int k = 0; k < 8; k++) {
                uint32_t addr = sb + OFF_X + r * 256 + (((2 * k + ah) ^ (r & 7)) * 16);
                LDMATRIX_X4(afr[mt][k], addr);
            }
        }
    }

    const int q  = lane & 3;   // col pair within n8
    const int rp = lane >> 2;  // row within 8
    const uint32_t br_ = lane & 7, bh = lane >> 3;  // B ldmatrix lane mapping
    const int barid = pair + 1;

    const __half2 mtwo = __float2half2_rn(-2.0f);
    const __half2 biginit = __float2half2_rn(60000.0f);
    __half2 rmin2[4] = {biginit, biginit, biginit, biginit};

    // ---- mainloop: pair-private two-stage pipeline over 8 sub-chunks
#pragma unroll 1
    for (int i = 0; i < NSUB; i++) {
        uint32_t buf = (i & 1) ? buf1 : buf0;
        asm volatile("cp.async.wait_group 0;" ::: "memory");
        asm volatile("bar.sync %0, 64;" :: "r"(barid) : "memory");
        if (i + 1 < NSUB)
            issue_sub((i & 1) ? buf0 : buf1, pbase, i + 1, tp);

        const __half2* pnb = (const __half2*)(smem + (buf - sb) + BUFBYTES);
        const uint32_t bl = buf + br_ * 256;
#pragma unroll
        for (int g = 0; g < 4; g++) {   // 4 n8-groups of this sub-chunk
            uint32_t acc[4] = {0u, 0u, 0u, 0u};
#pragma unroll
            for (int kk = 0; kk < 4; kk++) {      // pairs of k16 steps
                uint32_t bfr[4];
                uint32_t addr = bl + g * 2048 + (((4 * kk + bh) ^ br_) * 16);
                LDMATRIX_X4(bfr, addr);
                MMA16816H(acc + 0, afr[0][2 * kk],     bfr[0], bfr[1]);
                MMA16816H(acc + 2, afr[1][2 * kk],     bfr[0], bfr[1]);
                MMA16816H(acc + 0, afr[0][2 * kk + 1], bfr[2], bfr[3]);
                MMA16816H(acc + 2, afr[1][2 * kk + 1], bfr[2], bfr[3]);
            }
            __half2 pp = pnb[g * 4 + q];
            rmin2[0] = __hmin2(rmin2[0], __hfma2(mtwo, *(__half2*)&acc[0], pp));
            rmin2[1] = __hmin2(rmin2[1], __hfma2(mtwo, *(__half2*)&acc[1], pp));
            rmin2[2] = __hmin2(rmin2[2], __hfma2(mtwo, *(__half2*)&acc[2], pp));
            rmin2[3] = __hmin2(rmin2[3], __hfma2(mtwo, *(__half2*)&acc[3], pp));
        }
    }

    // ---- reduce across the lane-quad (4 col-pairs = 8 cols) within each warp
    float rmin[4];
#pragma unroll
    for (int i = 0; i < 4; i++) {
        uint32_t v = *(uint32_t*)&rmin2[i];
        uint32_t v1 = __shfl_xor_sync(0xffffffffu, v, 1);
        __half2 h = __hmin2(*(__half2*)&v, *(__half2*)&v1);
        uint32_t hv = *(uint32_t*)&h;
        uint32_t v2 = __shfl_xor_sync(0xffffffffu, hv, 2);
        h = __hmin2(h, *(__half2*)&v2);
        rmin[i] = fminf(__low2float(h), __high2float(h));
    }
    // rmin[i] = min over this pair's 256 pts for row mhalf*32 + i*8 + rp (q==0)

    // ---- combine the four pairs via smem; pair0 writes this CTA's half-min
    float* minbuf = (float*)(smem + OFF_MIN);   // [4][64]; [3] = CTA-combined
    if (pair > 0 && q == 0) {
#pragma unroll
        for (int i = 0; i < 4; i++)
            minbuf[(pair - 1) * 64 + mhalf * 32 + i * 8 + rp] = rmin[i];
    }
    __syncthreads();
    if (pair == 0 && q == 0) {
#pragma unroll
        for (int i = 0; i < 4; i++) {
            int rl = mhalf * 32 + i * 8 + rp;
            float mn = rmin[i];
            mn = fminf(mn, minbuf[rl]);
            mn = fminf(mn, minbuf[64 + rl]);
            mn = fminf(mn, minbuf[128 + rl]);
            minbuf[192 + rl] = mn;                       // CTA-combined (local)
            g_hmin[half * NROWS + row0 + rl] = mn;       // publish for peer
        }
        __threadfence();    // order half-min stores before the ticket
    }
    __syncthreads();

    // ---- ticket: last CTA of this tile fuses the sigmoid epilogue
    int* flag = (int*)(smem + OFF_FLAG);
    if (tid == 0) *flag = atomicAdd(&g_tick[tile], 1);
    __syncthreads();
    if (*flag == 1) {
        __threadfence();    // acquire peer's g_hmin writes
        if (tid < MTILE) {
            const float* xn_s = (const float*)(smem + OFF_XN);
            float brv  = beta_raw[0];
            float beta = fmaxf(brv, 0.f) + log1pf(__expf(-fabsf(brv)));
            float mn = fminf(minbuf[192 + tid],
                             g_hmin[(1 - half) * NROWS + row0 + tid]);
            float md = fmaxf(xn_s[tid] + mn, 0.f);
            float arg = (md - beta * LOG1000F) / beta;
            out[row0 + tid] = 1.f / (1.f + __expf(-arg));
        }
        if (tid == 0) g_tick[tile] = 0;   // reset for graph replay
    }
}

// ---------------------------------------------------------------------------
extern "C" void kernel_launch(void* const* d_in, const int* in_sizes, int n_in,
                              void* d_out, int out_size) {
    const float* x    = (const float*)d_in[0];   // [65536,128]
    const float* pts  = (const float*)d_in[1];   // [2048,128]
    const float* braw = (const float*)d_in[2];   // [1]
    float* out = (float*)d_out;                  // [65536]

    cudaFuncSetAttribute(distnet_main, cudaFuncAttributeMaxDynamicSharedMemorySize,
                         SMEM_BYTES);

    distnet_prep<<<NPTS, DIM>>>(pts);
    distnet_main<<<NTILES * 2, 256, SMEM_BYTES>>>(x, braw, out);
}

// round 17
// speedup vs baseline: 1.1941x; 1.1199x over previous
#include <cuda_runtime.h>
#include <cuda_fp16.h>
#include <cstdint>

// ============================================================================
// DistNet: out[n] = sigmoid((max(0, ||x||^2 + min_p(||p||^2 - 2 x.p)) + alpha)/beta)
// R17: R16 with the pipeline schedule FIXED (R16 deadlocked by double-issuing
// an mbarrier phase). Correct double-buffer invariant: prologue issues chunk
// 0; at iteration i: wait(i), bar, issue(i+1) into the other buffer — R7's
// proven schedule, but with ONE cp.async.bulk (8KB) per chunk instead of 512
// per-thread cp.async ops, removing the LDGSTS half of the MIO load.
// g_pts stored PRE-SWIZZLED at 8KB-chunk granularity; ||p||^2 preloaded once.
// ============================================================================

static constexpr int NROWS  = 65536;
static constexpr int DIM    = 128;
static constexpr int NPTS   = 2048;
static constexpr int MTILE  = 64;
static constexpr int SUBPTS = 32;            // points per sub-chunk (8KB)
static constexpr int NSUB   = 512 / SUBPTS;  // 16 sub-chunks per pair (512 pts)
static constexpr int CHUNKB = SUBPTS * 256;  // 8192

#define LOG1000F 6.9077542789816375f

// g_pts holds PRE-SWIZZLED 8KB chunks: chunk c = points [32c, 32c+32),
// element (n, 16B-unit u, byte b) at c*8192 + n*256 + ((u ^ (n&7))*16) + b.
__device__ __align__(16) __half g_pts[NPTS * DIM];
__device__ __align__(16) __half g_pn[NPTS];         // ||p||^2 (fp16), linear

// smem layout (dynamic)
static constexpr int OFF_X    = 0;                  // 64 x 256B = 16384
static constexpr int OFF_B    = 16384;              // 4 pairs x 2 bufs x 8KB
static constexpr int OFF_PN   = 16384 + 65536;      // 81920: whole pn (4KB)
static constexpr int OFF_XN   = OFF_PN + 4096;      // 86016: 64 floats
static constexpr int OFF_MIN  = OFF_XN + 256;       // 86272: 3x64 floats
static constexpr int OFF_MBAR = OFF_MIN + 768;      // 87040: 8 mbarriers
static constexpr int SMEM_BYTES = OFF_MBAR + 128;   // 87168 -> occ 2

// ---------------------------------------------------------------------------
__device__ __forceinline__ uint32_t smem_u32(const void* p) {
    uint32_t a;
    asm("{ .reg .u64 t; cvta.to.shared.u64 t, %1; cvt.u32.u64 %0, t; }"
        : "=r"(a) : "l"(p));
    return a;
}

#define LDMATRIX_X4(R, ADDR)                                                   \
    asm volatile("ldmatrix.sync.aligned.m8n8.x4.shared.b16 {%0,%1,%2,%3}, [%4];" \
                 : "=r"((R)[0]), "=r"((R)[1]), "=r"((R)[2]), "=r"((R)[3])       \
                 : "r"(ADDR))

#define MMA16816H(C, A, B0, B1)                                                \
    asm volatile("mma.sync.aligned.m16n8k16.row.col.f16.f16.f16.f16 "          \
                 "{%0,%1}, {%2,%3,%4,%5}, {%6,%7}, {%0,%1};"                   \
                 : "+r"((C)[0]), "+r"((C)[1])                                  \
                 : "r"((A)[0]), "r"((A)[1]), "r"((A)[2]), "r"((A)[3]),         \
                   "r"(B0), "r"(B1))

__device__ __forceinline__ void mbar_init(uint32_t addr, uint32_t cnt) {
    asm volatile("mbarrier.init.shared.b64 [%0], %1;" :: "r"(addr), "r"(cnt)
                 : "memory");
}

__device__ __forceinline__ void bulk_copy(uint32_t dst, const void* src,
                                          uint32_t bytes, uint32_t mbar) {
    asm volatile(
        "mbarrier.arrive.expect_tx.shared.b64 _, [%0], %1;" :: "r"(mbar),
        "r"(bytes) : "memory");
    asm volatile(
        "cp.async.bulk.shared::cta.global.mbarrier::complete_tx::bytes "
        "[%0], [%1], %2, [%3];"
        :: "r"(dst), "l"(src), "r"(bytes), "r"(mbar) : "memory");
}

__device__ __forceinline__ void mbar_wait(uint32_t addr, uint32_t parity) {
    asm volatile(
        "{\n\t"
        ".reg .pred P;\n\t"
        "WL_%=:\n\t"
        "mbarrier.try_wait.parity.acquire.cta.shared::cta.b64 P, [%0], %1, 0x989680;\n\t"
        "@P bra.uni WD_%=;\n\t"
        "bra.uni WL_%=;\n\t"
        "WD_%=:\n\t"
        "}"
        :: "r"(addr), "r"(parity) : "memory");
}

// ---------------------------------------------------------------------------
// Prep: points f32 -> fp16 PRE-SWIZZLED chunk layout + ||p||^2 (fp16)
__global__ void distnet_prep(const float* __restrict__ pts) {
    int p = blockIdx.x;
    int t = threadIdx.x;  // 128 = DIM
    float v = pts[p * DIM + t];
    {
        int chunk = p >> 5, n = p & 31;
        int u = t >> 3;                 // 16B unit 0..15
        g_pts[chunk * 4096 + n * 128 + ((u ^ (n & 7)) * 8) + (t & 7)] =
            __float2half(v);
    }
    float s = v * v;
#pragma unroll
    for (int o = 16; o > 0; o >>= 1) s += __shfl_xor_sync(0xffffffffu, s, o);
    __shared__ float ws[4];
    if ((t & 31) == 0) ws[t >> 5] = s;
    __syncthreads();
    if (t == 0) g_pn[p] = __float2half(ws[0] + ws[1] + ws[2] + ws[3]);
}

// ---------------------------------------------------------------------------
__global__ void __launch_bounds__(256, 2)
distnet_main(const float* __restrict__ x, const float* __restrict__ beta_raw,
             float* __restrict__ out) {
    extern __shared__ char smem[];
    const uint32_t sb = smem_u32(smem);
    const int tid   = threadIdx.x;
    const int lane  = tid & 31;
    const int wid   = tid >> 5;        // 0..7
    const int mhalf = wid & 1;         // m32 half of the 64-row tile
    const int pair  = wid >> 1;        // 0..3, owns chunks [16*pair, +16)
    const int row0  = blockIdx.x * MTILE;
    const bool leader = (mhalf == 0) && (lane == 0);   // one issuer per pair

    const uint32_t buf0  = sb + OFF_B + pair * (2 * CHUNKB);
    const uint32_t buf1  = buf0 + CHUNKB;
    const uint32_t mbar0 = sb + OFF_MBAR + pair * 16;
    const uint32_t mbar1 = mbar0 + 8;
    const int      cbase = pair * NSUB;  // first chunk index of this pair

    // ---- init mbarriers + preload pn, then first bulk copy (chunk 0 only)
    if (tid < 8) mbar_init(sb + OFF_MBAR + tid * 8, 1);
    ((uint4*)(smem + OFF_PN))[tid] = ((const uint4*)g_pn)[tid];  // 4KB
    __syncthreads();
    if (leader)
        bulk_copy(buf0, (const char*)g_pts + (size_t)cbase * CHUNKB,
                  CHUNKB, mbar0);

    // ---- X tile: 64 rows x 256B fp16, 4 threads per row + ||x||^2
    {
        int sub = tid & 3;
        int r   = tid >> 2;            // 0..63
        const float4* src = (const float4*)(x + (size_t)(row0 + r) * DIM);
        float s = 0.f;
#pragma unroll
        for (int j = 0; j < 4; j++) {
            int c = j * 4 + sub;       // 16B fp16 unit
            float4 v0 = src[c * 2], v1 = src[c * 2 + 1];
            s += v0.x * v0.x + v0.y * v0.y + v0.z * v0.z + v0.w * v0.w;
            s += v1.x * v1.x + v1.y * v1.y + v1.z * v1.z + v1.w * v1.w;
            __half2 p0 = __floats2half2_rn(v0.x, v0.y);
            __half2 p1 = __floats2half2_rn(v0.z, v0.w);
            __half2 p2 = __floats2half2_rn(v1.x, v1.y);
            __half2 p3 = __floats2half2_rn(v1.z, v1.w);
            uint4 pk;
            pk.x = *(uint32_t*)&p0; pk.y = *(uint32_t*)&p1;
            pk.z = *(uint32_t*)&p2; pk.w = *(uint32_t*)&p3;
            *(uint4*)(smem + OFF_X + r * 256 + ((c ^ (r & 7)) * 16)) = pk;
        }
        s += __shfl_xor_sync(0xffffffffu, s, 1);
        s += __shfl_xor_sync(0xffffffffu, s, 2);
        if (sub == 0) ((float*)(smem + OFF_XN))[r] = s;
    }
    __syncthreads();

    // ---- A fragments: warp owns rows mhalf*32..+31; load once
    uint32_t afr[2][8][4];
    {
        int ar = lane & 15, ah = lane >> 4;
#pragma unroll
        for (int mt = 0; mt < 2; mt++) {
            int r = mhalf * 32 + mt * 16 + ar;
#pragma unroll
            for (int k = 0; k < 8; k++) {
                uint32_t addr = sb + OFF_X + r * 256 + (((2 * k + ah) ^ (r & 7)) * 16);
                LDMATRIX_X4(afr[mt][k], addr);
            }
        }
    }

    const int q  = lane & 3;   // col pair within n8
    const int rp = lane >> 2;  // row within 8
    const uint32_t br_ = lane & 7, bh = lane >> 3;  // B ldmatrix lane mapping
    const int barid = pair + 1;
    const __half2* pnp = (const __half2*)(smem + OFF_PN) + pair * 256;

    const __half2 mtwo = __float2half2_rn(-2.0f);
    const __half2 biginit = __float2half2_rn(60000.0f);
    __half2 rmin2[4] = {biginit, biginit, biginit, biginit};

    // ---- mainloop: R7 schedule with bulk copies. At iter i: wait chunk i
    // (mbar[i%2], parity = usage_count/2 = (i>>1)&1), bar.sync (both warps
    // done with the OTHER buffer), leader issues chunk i+1 into it.
#pragma unroll 1
    for (int i = 0; i < NSUB; i++) {
        uint32_t buf  = (i & 1) ? buf1 : buf0;
        uint32_t mbar = (i & 1) ? mbar1 : mbar0;
        mbar_wait(mbar, (i >> 1) & 1);
        asm volatile("bar.sync %0, 64;" :: "r"(barid) : "memory");
        if (i + 1 < NSUB && leader)
            bulk_copy((i & 1) ? buf0 : buf1,
                      (const char*)g_pts + (size_t)(cbase + i + 1) * CHUNKB,
                      CHUNKB, (i & 1) ? mbar0 : mbar1);

        const __half2* pnb = pnp + i * 16;   // 32 pts = 16 half2
        const uint32_t bl = buf + br_ * 256;
#pragma unroll
        for (int g = 0; g < 4; g++) {   // 4 n8-groups of this sub-chunk
            uint32_t acc[4] = {0u, 0u, 0u, 0u};
#pragma unroll
            for (int kk = 0; kk < 4; kk++) {      // pairs of k16 steps
                uint32_t bfr[4];
                uint32_t addr = bl + g * 2048 + (((4 * kk + bh) ^ br_) * 16);
                LDMATRIX_X4(bfr, addr);
                MMA16816H(acc + 0, afr[0][2 * kk],     bfr[0], bfr[1]);
                MMA16816H(acc + 2, afr[1][2 * kk],     bfr[0], bfr[1]);
                MMA16816H(acc + 0, afr[0][2 * kk + 1], bfr[2], bfr[3]);
                MMA16816H(acc + 2, afr[1][2 * kk + 1], bfr[2], bfr[3]);
            }
            __half2 pp = pnb[g * 4 + q];
            rmin2[0] = __hmin2(rmin2[0], __hfma2(mtwo, *(__half2*)&acc[0], pp));
            rmin2[1] = __hmin2(rmin2[1], __hfma2(mtwo, *(__half2*)&acc[1], pp));
            rmin2[2] = __hmin2(rmin2[2], __hfma2(mtwo, *(__half2*)&acc[2], pp));
            rmin2[3] = __hmin2(rmin2[3], __hfma2(mtwo, *(__half2*)&acc[3], pp));
        }
    }

    // ---- reduce across the lane-quad (4 col-pairs = 8 cols) within each warp
    float rmin[4];
#pragma unroll
    for (int i = 0; i < 4; i++) {
        uint32_t v = *(uint32_t*)&rmin2[i];
        uint32_t v1 = __shfl_xor_sync(0xffffffffu, v, 1);
        __half2 h = __hmin2(*(__half2*)&v, *(__half2*)&v1);
        uint32_t hv = *(uint32_t*)&h;
        uint32_t v2 = __shfl_xor_sync(0xffffffffu, hv, 2);
        h = __hmin2(h, *(__half2*)&v2);
        rmin[i] = fminf(__low2float(h), __high2float(h));
    }
    // rmin[i] = min over this pair's 512 pts for row mhalf*32 + i*8 + rp (q==0)

    // ---- combine the four pairs via smem, then epilogue
    float* minbuf = (float*)(smem + OFF_MIN);   // [3][64]
    if (pair > 0 && q == 0) {
#pragma unroll
        for (int i = 0; i < 4; i++)
            minbuf[(pair - 1) * 64 + mhalf * 32 + i * 8 + rp] = rmin[i];
    }
    __syncthreads();
    if (pair == 0 && q == 0) {
        const float* xn_s = (const float*)(smem + OFF_XN);
        float brv  = beta_raw[0];
        float beta = fmaxf(brv, 0.f) + log1pf(__expf(-fabsf(brv)));  // softplus
#pragma unroll
        for (int i = 0; i < 4; i++) {
            int rl = mhalf * 32 + i * 8 + rp;
            float mn = rmin[i];
            mn = fminf(mn, minbuf[rl]);
            mn = fminf(mn, minbuf[64 + rl]);
            mn = fminf(mn, minbuf[128 + rl]);
            float md  = fmaxf(xn_s[rl] + mn, 0.f);
            float arg = (md - beta * LOG1000F) / beta;
            out[row0 + rl] = 1.f / (1.f + __expf(-arg));
        }
    }
}

// ---------------------------------------------------------------------------
extern "C" void kernel_launch(void* const* d_in, const int* in_sizes, int n_in,
                              void* d_out, int out_size) {
    const float* x    = (const float*)d_in[0];   // [65536,128]
    const float* pts  = (const float*)d_in[1];   // [2048,128]
    const float* braw = (const float*)d_in[2];   // [1]
    float* out = (float*)d_out;                  // [65536]

    cudaFuncSetAttribute(distnet_main, cudaFuncAttributeMaxDynamicSharedMemorySize,
                         SMEM_BYTES);

    distnet_prep<<<NPTS, DIM>>>(pts);
    distnet_main<<<NROWS / MTILE, 256, SMEM_BYTES>>>(x, braw, out);
}